// round 13
// baseline (speedup 1.0000x reference)
#include <cuda_runtime.h>
#include <cuda_bf16.h>
#include <cstdint>
#include <math.h>

// ---------------------------------------------------------------------------
// Problem constants
// ---------------------------------------------------------------------------
#define N_FEAT 131072
#define D      128
#define K      1024
#define TM     64             // rows per CTA
#define TN     128            // centers per B-tile
#define NTILE  (K / TN)       // 8
#define NBLK   (N_FEAT / TM)  // 2048

#define RAW_BYTES (TM * D * 4)     // 32768 raw fp32 rows (staged transiently)
#define A_BYTES   (TM * D * 2)     // 16384 bf16-hi tile (256B rows, persistent)
#define B_BYTES   (TN * D * 2)     // 32768 per B tile

// SMEM map (dynamic): ctrl 1KB + AH 16KB + B0 32KB + B1 32KB = 82944 bytes
// per-CTA granule cost = ceil((82944+1024)/8192)*8192 = 90112; x2 <= 233472 OK
#define SM_CTRL 0
#define SM_RINV 256
#define SM_AH   1024
#define SM_B0   (SM_AH + A_BYTES)          // 17408; ALSO transient RAW staging
#define SM_B1   (SM_B0 + B_BYTES)          // 50176
#define SMEM_TOTAL 82944
// epilogue scratch overlays the (dead) B0 region
#define SM_PB   SM_B0                       // 64 rows x 4 warp_n uints = 1KB
#define SM_BKS  (SM_B0 + 1024)
#define SM_LSUM (SM_B0 + 1536)
#define SM_SD   (SM_B0 + 2048)

#define MB_RAW 0
#define MB_B0  8
#define MB_B1  16

// ---------------------------------------------------------------------------
// Device scratch
// ---------------------------------------------------------------------------
__device__ __align__(1024) unsigned char g_B[NTILE * B_BYTES];  // 256 KB
__device__ float g_cnormsq[K];
__device__ float g_partial[NBLK];
__device__ unsigned int g_ctr;

// ---------------------------------------------------------------------------
// PTX helpers
// ---------------------------------------------------------------------------
__device__ __forceinline__ uint32_t smem_u32(const void* p) {
    uint32_t a;
    asm("{ .reg .u64 t; cvta.to.shared.u64 t, %1; cvt.u32.u64 %0, t; }" : "=r"(a) : "l"(p));
    return a;
}
#define MBAR_INIT(a, c) \
    asm volatile("mbarrier.init.shared.b64 [%0], %1;" :: "r"((uint32_t)(a)), "r"((uint32_t)(c)) : "memory")
#define MBAR_EXPECT_TX(a, b) \
    asm volatile("mbarrier.arrive.expect_tx.shared.b64 _, [%0], %1;" :: "r"((uint32_t)(a)), "r"((uint32_t)(b)) : "memory")
#define MBAR_WAIT(a, ph) do { \
    uint32_t _m = (uint32_t)(a), _p = (uint32_t)(ph), _d; \
    asm volatile("{ .reg .pred p; mbarrier.try_wait.parity.acquire.cta.shared::cta.b64 p, [%1], %2; selp.b32 %0,1,0,p; }" \
        : "=r"(_d) : "r"(_m), "r"(_p) : "memory"); \
    if (!_d) { \
        asm volatile("{ .reg .pred P1; WL%=: mbarrier.try_wait.parity.acquire.cta.shared::cta.b64 P1, [%0], %1, 0x989680; @P1 bra.uni WD%=; bra.uni WL%=; WD%=: }" \
            :: "r"(_m), "r"(_p) : "memory"); \
    } \
} while (0)

__device__ __forceinline__ void bulk_g2s(uint32_t dst, const void* src,
                                         uint32_t bytes, uint32_t mbar) {
    asm volatile(
        "cp.async.bulk.shared::cta.global.mbarrier::complete_tx::bytes [%0], [%1], %2, [%3];"
        :: "r"(dst), "l"(src), "r"(bytes), "r"(mbar) : "memory");
}
#define LDSM_X4(r, a) \
    asm volatile("ldmatrix.sync.aligned.m8n8.x4.shared.b16 {%0,%1,%2,%3}, [%4];" \
        : "=r"((r)[0]), "=r"((r)[1]), "=r"((r)[2]), "=r"((r)[3]) : "r"(a))
#define MMA_BF16(c, a, b0_, b1_) \
    asm volatile("mma.sync.aligned.m16n8k16.row.col.f32.bf16.bf16.f32 " \
        "{%0,%1,%2,%3}, {%4,%5,%6,%7}, {%8,%9}, {%0,%1,%2,%3};" \
        : "+f"((c)[0]), "+f"((c)[1]), "+f"((c)[2]), "+f"((c)[3]) \
        : "r"((a)[0]), "r"((a)[1]), "r"((a)[2]), "r"((a)[3]), "r"(b0_), "r"(b1_))

__device__ __forceinline__ unsigned short bf16_bits(__nv_bfloat16 h) {
    return *reinterpret_cast<unsigned short*>(&h);
}
__device__ __forceinline__ unsigned int pack_bf2(float a, float b) {
    return (unsigned)bf16_bits(__float2bfloat16(a)) |
           ((unsigned)bf16_bits(__float2bfloat16(b)) << 16);
}
__device__ __forceinline__ uint32_t umax32(uint32_t a, uint32_t b) {
    return a > b ? a : b;
}

// ---------------------------------------------------------------------------
// Prep: centers -> normalize; bf16-hi into g_B (layout unchanged)
// ---------------------------------------------------------------------------
__global__ void prep_centers(const float* __restrict__ centers) {
    int k = blockIdx.x;
    int d = threadIdx.x;
    float v = centers[k * D + d];
    float s = v * v;
    #pragma unroll
    for (int o = 16; o; o >>= 1) s += __shfl_down_sync(0xffffffffu, s, o);
    __shared__ float ws[4];
    if ((d & 31) == 0) ws[d >> 5] = s;
    __syncthreads();
    float tot  = ws[0] + ws[1] + ws[2] + ws[3];
    float norm = sqrtf(tot);
    float x = v / fmaxf(norm, 1e-12f);
    unsigned char* tile = g_B + (size_t)(k >> 7) * B_BYTES;
    int nn = k & 127;
    uint32_t off = (uint32_t)(nn * 256 + ((((d >> 3) ^ (nn & 7)) & 15) << 4) + (d & 7) * 2);
    *(unsigned short*)(tile + off) = bf16_bits(__float2bfloat16(x));
    if (d == 0) g_cnormsq[k] = tot;
}

// ---------------------------------------------------------------------------
// Main kernel: round-9 structure (2 CTAs/SM, double buffer, dist-2 prefetch,
// persistent AH + register-hoisted A) + round-12 packed argmax.
// ---------------------------------------------------------------------------
__global__ __launch_bounds__(256, 2)
void gemm_argmax_mma(const float* __restrict__ features,
                     const float* __restrict__ centers,
                     float* __restrict__ out) {
    extern __shared__ __align__(1024) unsigned char smem[];
    uint32_t sb = smem_u32(smem);
    const int tid = threadIdx.x;
    const int wid = tid >> 5, l = tid & 31;
    const int warp_m = wid >> 2, warp_n = wid & 3;

    if (tid == 0) {
        MBAR_INIT(sb + SM_CTRL + MB_RAW, 1);
        MBAR_INIT(sb + SM_CTRL + MB_B0, 1);
        MBAR_INIT(sb + SM_CTRL + MB_B1, 1);
    }
    __syncthreads();
    // Stage raw fp32 rows into the (not-yet-used) B0 region
    if (tid == 0) {
        MBAR_EXPECT_TX(sb + SM_CTRL + MB_RAW, RAW_BYTES);
        bulk_g2s(sb + SM_B0, features + (size_t)blockIdx.x * TM * D,
                 RAW_BYTES, sb + SM_CTRL + MB_RAW);
    }

    // ---- A prep: 4 threads per row, raw read from B0 staging ----
    MBAR_WAIT(sb + SM_CTRL + MB_RAW, 0);
    {
        const int row = tid >> 2, q = tid & 3;
        const float4* raw4 = (const float4*)(smem + SM_B0 + row * 512);
        float s = 0.0f;
        #pragma unroll
        for (int j = 0; j < 8; j++) {
            float4 v = raw4[q * 8 + ((j + row) & 7)];
            s += v.x * v.x + v.y * v.y + v.z * v.z + v.w * v.w;
        }
        s += __shfl_xor_sync(0xffffffffu, s, 1);
        s += __shfl_xor_sync(0xffffffffu, s, 2);
        float rinv = 1.0f / fmaxf(sqrtf(s), 1e-12f);
        if (q == 0) ((float*)(smem + SM_RINV))[row] = rinv;
        unsigned char* arow = smem + SM_AH + row * 256;
        #pragma unroll
        for (int cc = 0; cc < 4; cc++) {
            int c = q * 4 + cc;
            float4 a0 = raw4[c * 2];
            float4 a1 = raw4[c * 2 + 1];
            uint4 o;
            o.x = pack_bf2(a0.x * rinv, a0.y * rinv);
            o.y = pack_bf2(a0.z * rinv, a0.w * rinv);
            o.z = pack_bf2(a1.x * rinv, a1.y * rinv);
            o.w = pack_bf2(a1.z * rinv, a1.w * rinv);
            int fc = c ^ (row & 7);
            *(uint4*)(arow + (fc << 4)) = o;
        }
    }
    __syncthreads();   // all raw reads done; B0 region reusable

    // Kick both B buffers
    if (tid == 0) {
        MBAR_EXPECT_TX(sb + SM_CTRL + MB_B0, B_BYTES);
        bulk_g2s(sb + SM_B0, g_B, B_BYTES, sb + SM_CTRL + MB_B0);
        MBAR_EXPECT_TX(sb + SM_CTRL + MB_B1, B_BYTES);
        bulk_g2s(sb + SM_B1, g_B + B_BYTES, B_BYTES, sb + SM_CTRL + MB_B1);
    }

    const int a_row_in = (l & 7) + ((l >> 3) & 1) * 8;
    const int a_cb     = (l >> 4);
    const int b_row_in = (l & 7) + ((l >> 4) & 1) * 8;
    const int b_cb     = (l >> 3) & 1;

    // ---- Hoist ALL A fragments into registers (AH is persistent; no race) ----
    uint32_t afr[8][2][4];   // [kk][mi][frag]
    #pragma unroll
    for (int kk = 0; kk < 8; kk++) {
        #pragma unroll
        for (int mi = 0; mi < 2; mi++) {
            int row = warp_m * 32 + mi * 16 + a_row_in;
            uint32_t addr = sb + SM_AH + row * 256 +
                            (((kk * 2 + a_cb) ^ (row & 7)) << 4);
            LDSM_X4(afr[kk][mi], addr);
        }
    }

    // Packed argmax running best: bits(sim+2) & ~1023 | (1023-k)
    uint32_t pbest[4] = {0u, 0u, 0u, 0u};

    for (int t = 0; t < NTILE; t++) {
        const uint32_t bbuf = (t & 1) ? (sb + SM_B1) : (sb + SM_B0);
        MBAR_WAIT(sb + SM_CTRL + ((t & 1) ? MB_B1 : MB_B0), (t >> 1) & 1);

        float acc[2][4][4];
        #pragma unroll
        for (int mi = 0; mi < 2; mi++)
            #pragma unroll
            for (int ni = 0; ni < 4; ni++)
                #pragma unroll
                for (int e2 = 0; e2 < 4; e2++) acc[mi][ni][e2] = 0.0f;

        #pragma unroll
        for (int kk = 0; kk < 8; kk++) {
            uint32_t bfm[2][4];
            #pragma unroll
            for (int bp = 0; bp < 2; bp++) {
                int nrow = warp_n * 32 + bp * 16 + b_row_in;
                uint32_t addr = bbuf + nrow * 256 +
                                (((kk * 2 + b_cb) ^ (nrow & 7)) << 4);
                LDSM_X4(bfm[bp], addr);
            }
            #pragma unroll
            for (int mi = 0; mi < 2; mi++)
                #pragma unroll
                for (int ni = 0; ni < 4; ni++)
                    MMA_BF16(acc[mi][ni], afr[kk][mi],
                             bfm[ni >> 1][(ni & 1) * 2], bfm[ni >> 1][(ni & 1) * 2 + 1]);
        }

        // fold tile into packed argmax (flat FADD/LOP3/IMNMX, no pred chains)
        const uint32_t kvb = 1023u - (uint32_t)(t * TN + warp_n * 32 + (l & 3) * 2);
        #pragma unroll
        for (int mi = 0; mi < 2; mi++) {
            #pragma unroll
            for (int ni = 0; ni < 4; ni++) {
                uint32_t kv = kvb - (uint32_t)(ni * 8);
                uint32_t p0 = (__float_as_uint(acc[mi][ni][0] + 2.0f) & 0xFFFFFC00u) | kv;
                uint32_t p1 = (__float_as_uint(acc[mi][ni][1] + 2.0f) & 0xFFFFFC00u) | (kv - 1u);
                uint32_t p2 = (__float_as_uint(acc[mi][ni][2] + 2.0f) & 0xFFFFFC00u) | kv;
                uint32_t p3 = (__float_as_uint(acc[mi][ni][3] + 2.0f) & 0xFFFFFC00u) | (kv - 1u);
                pbest[mi * 2]     = umax32(pbest[mi * 2],     umax32(p0, p1));
                pbest[mi * 2 + 1] = umax32(pbest[mi * 2 + 1], umax32(p2, p3));
            }
        }

        __syncthreads();   // all warps done with this buffer -> refill with t+2
        if (tid == 0 && t + 2 < NTILE) {
            uint32_t mb = sb + SM_CTRL + ((t & 1) ? MB_B1 : MB_B0);
            MBAR_EXPECT_TX(mb, B_BYTES);
            bulk_g2s(bbuf, g_B + (size_t)(t + 2) * B_BYTES, B_BYTES, mb);
        }
    }

    // Cross-lane reduce (lanes sharing a row), then cross-warp_n via smem
    #pragma unroll
    for (int s2 = 0; s2 < 4; s2++) {
        pbest[s2] = umax32(pbest[s2], __shfl_xor_sync(0xffffffffu, pbest[s2], 1));
        pbest[s2] = umax32(pbest[s2], __shfl_xor_sync(0xffffffffu, pbest[s2], 2));
    }
    uint32_t* pb = (uint32_t*)(smem + SM_PB);
    if ((l & 3) == 0) {
        #pragma unroll
        for (int mi = 0; mi < 2; mi++)
            #pragma unroll
            for (int h = 0; h < 2; h++) {
                int row = warp_m * 32 + mi * 16 + (l >> 2) + h * 8;
                pb[row * 4 + warp_n] = pbest[mi * 2 + h];
            }
    }
    __syncthreads();
    int* bks = (int*)(smem + SM_BKS);
    if (tid < TM) {
        uint32_t m = umax32(umax32(pb[tid * 4 + 0], pb[tid * 4 + 1]),
                            umax32(pb[tid * 4 + 2], pb[tid * 4 + 3]));
        bks[tid] = 1023 - (int)(m & 1023u);
    }
    __syncthreads();
    // EXACT loss: 4 threads/row; features re-read from global (L2/HBM)
    float* lsum = (float*)(smem + SM_LSUM);
    {
        const int row = tid >> 2, q = tid & 3;
        const int bk  = bks[row];
        const float4* frow = (const float4*)(features + (size_t)(blockIdx.x * TM + row) * D);
        const float4* crow = (const float4*)(centers + (size_t)bk * D);
        float dot = 0.0f;
        #pragma unroll
        for (int j = 0; j < 8; j++) {
            int i4 = q * 8 + j;
            float4 a = frow[i4];
            float4 c = crow[i4];
            dot += a.x * c.x + a.y * c.y + a.z * c.z + a.w * c.w;
        }
        dot += __shfl_xor_sync(0xffffffffu, dot, 1);
        dot += __shfl_xor_sync(0xffffffffu, dot, 2);
        if (q == 0) {
            float rinv = ((float*)(smem + SM_RINV))[row];
            lsum[row] = 1.0f + g_cnormsq[bk] - 2.0f * rinv * dot;
        }
    }
    __syncthreads();
    #pragma unroll
    for (int s = TM / 2; s > 0; s >>= 1) {
        if (tid < s) lsum[tid] += lsum[tid + s];
        __syncthreads();
    }

    __shared__ unsigned int is_last;
    if (tid == 0) {
        g_partial[blockIdx.x] = lsum[0];
        __threadfence();
        is_last = (atomicAdd(&g_ctr, 1u) == NBLK - 1u);
    }
    __syncthreads();

    if (is_last) {
        __threadfence();
        double* sd = (double*)(smem + SM_SD);
        double s = 0.0;
        for (int i = tid; i < NBLK; i += 256)
            s += (double)(*(volatile float*)&g_partial[i]);
        sd[tid] = s;
        __syncthreads();
        for (int st = 128; st > 0; st >>= 1) {
            if (tid < st) sd[tid] += sd[tid + st];
            __syncthreads();
        }
        if (tid == 0) {
            out[0] = (float)(sd[0] / (double)N_FEAT);
            g_ctr = 0;
        }
    }
}

extern "C" void kernel_launch(void* const* d_in, const int* in_sizes, int n_in,
                              void* d_out, int out_size) {
    const float* features = (const float*)d_in[0];
    const float* centers  = (const float*)d_in[1];
    float* out = (float*)d_out;

    cudaFuncSetAttribute(gemm_argmax_mma,
                         cudaFuncAttributeMaxDynamicSharedMemorySize, SMEM_TOTAL);

    prep_centers<<<K, D>>>(centers);
    gemm_argmax_mma<<<NBLK, 256, SMEM_TOTAL>>>(features, centers, out);
}

// round 14
// speedup vs baseline: 1.3595x; 1.3595x over previous
#include <cuda_runtime.h>
#include <cuda_bf16.h>
#include <cstdint>
#include <math.h>

// ---------------------------------------------------------------------------
// Problem constants
// ---------------------------------------------------------------------------
#define N_FEAT 131072
#define D      128
#define K      1024
#define TM     128            // rows per CTA (512 threads, 16 warps)
#define TN     128            // centers per B-tile
#define NTILE  (K / TN)       // 8
#define NBLK   (N_FEAT / TM)  // 1024
#define NTHR   512

#define RAW_BYTES (TM * D * 4)     // 65536 raw fp32 rows (staged across B0+B1)
#define A_BYTES   (TM * D * 2)     // 32768 bf16-hi tile (256B rows, persistent)
#define B_BYTES   (TN * D * 2)     // 32768 per B tile

// SMEM map (dynamic): ctrl 1KB + AH 32KB + B0 32KB + B1 32KB = 99328 bytes
// 1 CTA/SM (512 thr x 128 regs = full regfile)
#define SM_CTRL 0
#define SM_RINV 256                 // 128 floats -> 256..768
#define SM_AH   1024
#define SM_B0   (SM_AH + A_BYTES)   // 33792; ALSO raw staging (with B1)
#define SM_B1   (SM_B0 + B_BYTES)   // 66560
#define SMEM_TOTAL 99328
// epilogue scratch overlays the (dead) B0 region
#define SM_REDS SM_B0                       // 128*16 floats = 8KB
#define SM_REDI (SM_B0 + 8192)              // 128*16 ints   = 8KB
#define SM_BKS  (SM_B0 + 16384)             // 128 ints
#define SM_LSUM (SM_B0 + 16896)             // 128 floats
#define SM_SD   (SM_B0 + 17408)             // 512 doubles = 4KB

#define MB_RAW 0
#define MB_B0  8
#define MB_B1  16

// ---------------------------------------------------------------------------
// Device scratch
// ---------------------------------------------------------------------------
__device__ __align__(1024) unsigned char g_B[NTILE * B_BYTES];  // 256 KB
__device__ float g_cnormsq[K];
__device__ float g_partial[NBLK];
__device__ unsigned int g_ctr;

// ---------------------------------------------------------------------------
// PTX helpers
// ---------------------------------------------------------------------------
__device__ __forceinline__ uint32_t smem_u32(const void* p) {
    uint32_t a;
    asm("{ .reg .u64 t; cvta.to.shared.u64 t, %1; cvt.u32.u64 %0, t; }" : "=r"(a) : "l"(p));
    return a;
}
#define MBAR_INIT(a, c) \
    asm volatile("mbarrier.init.shared.b64 [%0], %1;" :: "r"((uint32_t)(a)), "r"((uint32_t)(c)) : "memory")
#define MBAR_EXPECT_TX(a, b) \
    asm volatile("mbarrier.arrive.expect_tx.shared.b64 _, [%0], %1;" :: "r"((uint32_t)(a)), "r"((uint32_t)(b)) : "memory")
#define MBAR_WAIT(a, ph) do { \
    uint32_t _m = (uint32_t)(a), _p = (uint32_t)(ph), _d; \
    asm volatile("{ .reg .pred p; mbarrier.try_wait.parity.acquire.cta.shared::cta.b64 p, [%1], %2; selp.b32 %0,1,0,p; }" \
        : "=r"(_d) : "r"(_m), "r"(_p) : "memory"); \
    if (!_d) { \
        asm volatile("{ .reg .pred P1; WL%=: mbarrier.try_wait.parity.acquire.cta.shared::cta.b64 P1, [%0], %1, 0x989680; @P1 bra.uni WD%=; bra.uni WL%=; WD%=: }" \
            :: "r"(_m), "r"(_p) : "memory"); \
    } \
} while (0)

__device__ __forceinline__ void bulk_g2s(uint32_t dst, const void* src,
                                         uint32_t bytes, uint32_t mbar) {
    asm volatile(
        "cp.async.bulk.shared::cta.global.mbarrier::complete_tx::bytes [%0], [%1], %2, [%3];"
        :: "r"(dst), "l"(src), "r"(bytes), "r"(mbar) : "memory");
}
#define LDSM_X4(r, a) \
    asm volatile("ldmatrix.sync.aligned.m8n8.x4.shared.b16 {%0,%1,%2,%3}, [%4];" \
        : "=r"((r)[0]), "=r"((r)[1]), "=r"((r)[2]), "=r"((r)[3]) : "r"(a))
#define MMA_BF16(c, a, b0_, b1_) \
    asm volatile("mma.sync.aligned.m16n8k16.row.col.f32.bf16.bf16.f32 " \
        "{%0,%1,%2,%3}, {%4,%5,%6,%7}, {%8,%9}, {%0,%1,%2,%3};" \
        : "+f"((c)[0]), "+f"((c)[1]), "+f"((c)[2]), "+f"((c)[3]) \
        : "r"((a)[0]), "r"((a)[1]), "r"((a)[2]), "r"((a)[3]), "r"(b0_), "r"(b1_))

__device__ __forceinline__ unsigned short bf16_bits(__nv_bfloat16 h) {
    return *reinterpret_cast<unsigned short*>(&h);
}
__device__ __forceinline__ unsigned int pack_bf2(float a, float b) {
    return (unsigned)bf16_bits(__float2bfloat16(a)) |
           ((unsigned)bf16_bits(__float2bfloat16(b)) << 16);
}

// ---------------------------------------------------------------------------
// Prep: centers -> normalize; bf16-hi into g_B (layout unchanged)
// ---------------------------------------------------------------------------
__global__ void prep_centers(const float* __restrict__ centers) {
    int k = blockIdx.x;
    int d = threadIdx.x;
    float v = centers[k * D + d];
    float s = v * v;
    #pragma unroll
    for (int o = 16; o; o >>= 1) s += __shfl_down_sync(0xffffffffu, s, o);
    __shared__ float ws[4];
    if ((d & 31) == 0) ws[d >> 5] = s;
    __syncthreads();
    float tot  = ws[0] + ws[1] + ws[2] + ws[3];
    float norm = sqrtf(tot);
    float x = v / fmaxf(norm, 1e-12f);
    unsigned char* tile = g_B + (size_t)(k >> 7) * B_BYTES;
    int nn = k & 127;
    uint32_t off = (uint32_t)(nn * 256 + ((((d >> 3) ^ (nn & 7)) & 15) << 4) + (d & 7) * 2);
    *(unsigned short*)(tile + off) = bf16_bits(__float2bfloat16(x));
    if (d == 0) g_cnormsq[k] = tot;
}

// ---------------------------------------------------------------------------
// Main kernel: TM=128, 512 threads (16 warps), 1 CTA/SM.
// Same per-warp workload as round 9 (warp tile 32x32, A hoisted), but B-tile
// L2 traffic and per-SM bulk service halved.
// warp_m = wid>>2 in 0..3 (32 rows each), warp_n = wid&3 (32 cols each)
// ---------------------------------------------------------------------------
__global__ __launch_bounds__(NTHR, 1)
void gemm_argmax_mma(const float* __restrict__ features,
                     const float* __restrict__ centers,
                     float* __restrict__ out) {
    extern __shared__ __align__(1024) unsigned char smem[];
    uint32_t sb = smem_u32(smem);
    const int tid = threadIdx.x;
    const int wid = tid >> 5, l = tid & 31;
    const int warp_m = wid >> 2, warp_n = wid & 3;

    if (tid == 0) {
        MBAR_INIT(sb + SM_CTRL + MB_RAW, 1);
        MBAR_INIT(sb + SM_CTRL + MB_B0, 1);
        MBAR_INIT(sb + SM_CTRL + MB_B1, 1);
    }
    __syncthreads();
    // Stage raw fp32 rows (64KB) across the not-yet-used B0+B1 region
    if (tid == 0) {
        MBAR_EXPECT_TX(sb + SM_CTRL + MB_RAW, RAW_BYTES);
        bulk_g2s(sb + SM_B0, features + (size_t)blockIdx.x * TM * D,
                 RAW_BYTES, sb + SM_CTRL + MB_RAW);
    }

    // ---- A prep: 4 threads per row (128 rows x 4 = 512 threads) ----
    MBAR_WAIT(sb + SM_CTRL + MB_RAW, 0);
    {
        const int row = tid >> 2, q = tid & 3;
        const float4* raw4 = (const float4*)(smem + SM_B0 + row * 512);
        float s = 0.0f;
        #pragma unroll
        for (int j = 0; j < 8; j++) {
            float4 v = raw4[q * 8 + ((j + row) & 7)];
            s += v.x * v.x + v.y * v.y + v.z * v.z + v.w * v.w;
        }
        s += __shfl_xor_sync(0xffffffffu, s, 1);
        s += __shfl_xor_sync(0xffffffffu, s, 2);
        float rinv = 1.0f / fmaxf(sqrtf(s), 1e-12f);
        if (q == 0) ((float*)(smem + SM_RINV))[row] = rinv;
        unsigned char* arow = smem + SM_AH + row * 256;
        #pragma unroll
        for (int cc = 0; cc < 4; cc++) {
            int c = q * 4 + cc;                 // logical chunk: dims c*8..c*8+7
            float4 a0 = raw4[c * 2];
            float4 a1 = raw4[c * 2 + 1];
            uint4 o;
            o.x = pack_bf2(a0.x * rinv, a0.y * rinv);
            o.y = pack_bf2(a0.z * rinv, a0.w * rinv);
            o.z = pack_bf2(a1.x * rinv, a1.y * rinv);
            o.w = pack_bf2(a1.z * rinv, a1.w * rinv);
            int fc = c ^ (row & 7);
            *(uint4*)(arow + (fc << 4)) = o;
        }
    }
    __syncthreads();   // all raw reads done; B0/B1 regions reusable

    // Kick both B buffers
    if (tid == 0) {
        MBAR_EXPECT_TX(sb + SM_CTRL + MB_B0, B_BYTES);
        bulk_g2s(sb + SM_B0, g_B, B_BYTES, sb + SM_CTRL + MB_B0);
        MBAR_EXPECT_TX(sb + SM_CTRL + MB_B1, B_BYTES);
        bulk_g2s(sb + SM_B1, g_B + B_BYTES, B_BYTES, sb + SM_CTRL + MB_B1);
    }

    const int a_row_in = (l & 7) + ((l >> 3) & 1) * 8;
    const int a_cb     = (l >> 4);
    const int b_row_in = (l & 7) + ((l >> 4) & 1) * 8;
    const int b_cb     = (l >> 3) & 1;

    // ---- Hoist ALL A fragments into registers (AH persistent; no race) ----
    uint32_t afr[8][2][4];   // [kk][mi][frag]
    #pragma unroll
    for (int kk = 0; kk < 8; kk++) {
        #pragma unroll
        for (int mi = 0; mi < 2; mi++) {
            int row = warp_m * 32 + mi * 16 + a_row_in;
            uint32_t addr = sb + SM_AH + row * 256 +
                            (((kk * 2 + a_cb) ^ (row & 7)) << 4);
            LDSM_X4(afr[kk][mi], addr);
        }
    }

    float best[4];
    int   bidx[4];
    #pragma unroll
    for (int i = 0; i < 4; i++) { best[i] = -1e30f; bidx[i] = 0; }

    for (int t = 0; t < NTILE; t++) {
        const uint32_t bbuf = (t & 1) ? (sb + SM_B1) : (sb + SM_B0);
        MBAR_WAIT(sb + SM_CTRL + ((t & 1) ? MB_B1 : MB_B0), (t >> 1) & 1);

        float acc[2][4][4];
        #pragma unroll
        for (int mi = 0; mi < 2; mi++)
            #pragma unroll
            for (int ni = 0; ni < 4; ni++)
                #pragma unroll
                for (int e2 = 0; e2 < 4; e2++) acc[mi][ni][e2] = 0.0f;

        #pragma unroll
        for (int kk = 0; kk < 8; kk++) {
            uint32_t bfm[2][4];
            #pragma unroll
            for (int bp = 0; bp < 2; bp++) {
                int nrow = warp_n * 32 + bp * 16 + b_row_in;
                uint32_t addr = bbuf + nrow * 256 +
                                (((kk * 2 + b_cb) ^ (nrow & 7)) << 4);
                LDSM_X4(bfm[bp], addr);
            }
            #pragma unroll
            for (int mi = 0; mi < 2; mi++)
                #pragma unroll
                for (int ni = 0; ni < 4; ni++)
                    MMA_BF16(acc[mi][ni], afr[kk][mi],
                             bfm[ni >> 1][(ni & 1) * 2], bfm[ni >> 1][(ni & 1) * 2 + 1]);
        }

        // predicated fold (round-9 proven codegen)
        #pragma unroll
        for (int mi = 0; mi < 2; mi++) {
            #pragma unroll
            for (int ni = 0; ni < 4; ni++) {
                int k0 = t * TN + warp_n * 32 + ni * 8 + (l & 3) * 2;
                float c0 = acc[mi][ni][0], c1 = acc[mi][ni][1];
                float c2 = acc[mi][ni][2], c3 = acc[mi][ni][3];
                int i0 = mi * 2, i1 = mi * 2 + 1;
                if (c0 > best[i0]) { best[i0] = c0; bidx[i0] = k0; }
                if (c1 > best[i0]) { best[i0] = c1; bidx[i0] = k0 + 1; }
                if (c2 > best[i1]) { best[i1] = c2; bidx[i1] = k0; }
                if (c3 > best[i1]) { best[i1] = c3; bidx[i1] = k0 + 1; }
            }
        }
        __syncthreads();   // buffer free -> refill with tile t+2
        if (tid == 0 && t + 2 < NTILE) {
            uint32_t mb = sb + SM_CTRL + ((t & 1) ? MB_B1 : MB_B0);
            MBAR_EXPECT_TX(mb, B_BYTES);
            bulk_g2s(bbuf, g_B + (size_t)(t + 2) * B_BYTES, B_BYTES, mb);
        }
    }

    float* red_s = (float*)(smem + SM_REDS);
    int*   red_i = (int*)(smem + SM_REDI);
    int*   bks   = (int*)(smem + SM_BKS);
    float* lsum  = (float*)(smem + SM_LSUM);
    const int e = warp_n * 4 + (l & 3);
    #pragma unroll
    for (int mi = 0; mi < 2; mi++) {
        #pragma unroll
        for (int h = 0; h < 2; h++) {
            int row = warp_m * 32 + mi * 16 + (l >> 2) + h * 8;
            red_s[row * 16 + e] = best[mi * 2 + h];
            red_i[row * 16 + e] = bidx[mi * 2 + h];
        }
    }
    __syncthreads();
    if (tid < TM) {
        float bs = -1e30f; int bk = 0;
        #pragma unroll
        for (int q = 0; q < 16; q++) {
            float s = red_s[tid * 16 + q];
            int   k = red_i[tid * 16 + q];
            if (s > bs || (s == bs && k < bk)) { bs = s; bk = k; }
        }
        bks[tid] = bk;
    }
    __syncthreads();
    // EXACT loss: 4 threads/row; features re-read from global (L2/HBM)
    {
        const int row = tid >> 2, q = tid & 3;
        const int bk  = bks[row];
        const float4* frow = (const float4*)(features + (size_t)(blockIdx.x * TM + row) * D);
        const float4* crow = (const float4*)(centers + (size_t)bk * D);
        float dot = 0.0f;
        #pragma unroll
        for (int j = 0; j < 8; j++) {
            int i4 = q * 8 + j;
            float4 a = frow[i4];
            float4 c = crow[i4];
            dot += a.x * c.x + a.y * c.y + a.z * c.z + a.w * c.w;
        }
        dot += __shfl_xor_sync(0xffffffffu, dot, 1);
        dot += __shfl_xor_sync(0xffffffffu, dot, 2);
        if (q == 0) {
            float rinv = ((float*)(smem + SM_RINV))[row];
            lsum[row] = 1.0f + g_cnormsq[bk] - 2.0f * rinv * dot;
        }
    }
    __syncthreads();
    #pragma unroll
    for (int s = TM / 2; s > 0; s >>= 1) {
        if (tid < s) lsum[tid] += lsum[tid + s];
        __syncthreads();
    }

    __shared__ unsigned int is_last;
    if (tid == 0) {
        g_partial[blockIdx.x] = lsum[0];
        __threadfence();
        is_last = (atomicAdd(&g_ctr, 1u) == NBLK - 1u);
    }
    __syncthreads();

    if (is_last) {
        __threadfence();
        double* sd = (double*)(smem + SM_SD);
        double s = 0.0;
        for (int i = tid; i < NBLK; i += NTHR)
            s += (double)(*(volatile float*)&g_partial[i]);
        sd[tid] = s;
        __syncthreads();
        for (int st = NTHR / 2; st > 0; st >>= 1) {
            if (tid < st) sd[tid] += sd[tid + st];
            __syncthreads();
        }
        if (tid == 0) {
            out[0] = (float)(sd[0] / (double)N_FEAT);
            g_ctr = 0;
        }
    }
}

extern "C" void kernel_launch(void* const* d_in, const int* in_sizes, int n_in,
                              void* d_out, int out_size) {
    const float* features = (const float*)d_in[0];
    const float* centers  = (const float*)d_in[1];
    float* out = (float*)d_out;

    cudaFuncSetAttribute(gemm_argmax_mma,
                         cudaFuncAttributeMaxDynamicSharedMemorySize, SMEM_TOTAL);

    prep_centers<<<K, D>>>(centers);
    gemm_argmax_mma<<<NBLK, NTHR, SMEM_TOTAL>>>(features, centers, out);
}

// round 16
// speedup vs baseline: 1.5042x; 1.1064x over previous
#include <cuda_runtime.h>
#include <cuda_bf16.h>
#include <cstdint>
#include <math.h>

// ---------------------------------------------------------------------------
// Problem constants
// ---------------------------------------------------------------------------
#define N_FEAT 131072
#define D      128
#define K      1024
#define TM     64             // rows per CTA
#define TN     128            // centers per B-tile
#define NTILE  (K / TN)       // 8
#define NBLK   (N_FEAT / TM)  // 2048

#define RAW_BYTES (TM * D * 4)     // 32768 raw fp32 rows (staged transiently)
#define A_BYTES   (TM * D * 2)     // 16384 bf16-hi tile (256B rows, persistent)
#define B_BYTES   (TN * D * 2)     // 32768 per B tile

// SMEM map (dynamic): ctrl 1KB + AH 16KB + B0 32KB + B1 32KB = 82944 bytes
// per-CTA granule cost = ceil((82944+1024)/8192)*8192 = 90112; x2 fits -> 2 CTAs/SM
#define SM_CTRL 0
#define SM_RINV 256
#define SM_AH   1024
#define SM_B0   (SM_AH + A_BYTES)          // 17408; ALSO transient RAW staging
#define SM_B1   (SM_B0 + B_BYTES)          // 50176
#define SMEM_TOTAL 82944
// epilogue scratch overlays the (dead) B0 region
#define SM_REDS SM_B0
#define SM_REDI (SM_B0 + 4096)
#define SM_BKS  (SM_B0 + 8192)
#define SM_LSUM (SM_B0 + 8448)
#define SM_SD   (SM_B0 + 9216)

#define MB_RAW 0
#define MB_B0  8
#define MB_B1  16

// ---------------------------------------------------------------------------
// Device scratch
// ---------------------------------------------------------------------------
__device__ __align__(1024) unsigned char g_B[NTILE * B_BYTES];  // 256 KB
__device__ float g_cnormsq[K];
__device__ float g_partial[NBLK];
__device__ unsigned int g_ctr;

// ---------------------------------------------------------------------------
// PTX helpers
// ---------------------------------------------------------------------------
__device__ __forceinline__ uint32_t smem_u32(const void* p) {
    uint32_t a;
    asm("{ .reg .u64 t; cvta.to.shared.u64 t, %1; cvt.u32.u64 %0, t; }" : "=r"(a) : "l"(p));
    return a;
}
#define MBAR_INIT(a, c) \
    asm volatile("mbarrier.init.shared.b64 [%0], %1;" :: "r"((uint32_t)(a)), "r"((uint32_t)(c)) : "memory")
#define MBAR_EXPECT_TX(a, b) \
    asm volatile("mbarrier.arrive.expect_tx.shared.b64 _, [%0], %1;" :: "r"((uint32_t)(a)), "r"((uint32_t)(b)) : "memory")
#define MBAR_WAIT(a, ph) do { \
    uint32_t _m = (uint32_t)(a), _p = (uint32_t)(ph), _d; \
    asm volatile("{ .reg .pred p; mbarrier.try_wait.parity.acquire.cta.shared::cta.b64 p, [%1], %2; selp.b32 %0,1,0,p; }" \
        : "=r"(_d) : "r"(_m), "r"(_p) : "memory"); \
    if (!_d) { \
        asm volatile("{ .reg .pred P1; WL%=: mbarrier.try_wait.parity.acquire.cta.shared::cta.b64 P1, [%0], %1, 0x989680; @P1 bra.uni WD%=; bra.uni WL%=; WD%=: }" \
            :: "r"(_m), "r"(_p) : "memory"); \
    } \
} while (0)

__device__ __forceinline__ void bulk_g2s(uint32_t dst, const void* src,
                                         uint32_t bytes, uint32_t mbar) {
    asm volatile(
        "cp.async.bulk.shared::cta.global.mbarrier::complete_tx::bytes [%0], [%1], %2, [%3];"
        :: "r"(dst), "l"(src), "r"(bytes), "r"(mbar) : "memory");
}
#define LDSM_X4(r, a) \
    asm volatile("ldmatrix.sync.aligned.m8n8.x4.shared.b16 {%0,%1,%2,%3}, [%4];" \
        : "=r"((r)[0]), "=r"((r)[1]), "=r"((r)[2]), "=r"((r)[3]) : "r"(a))
#define MMA_BF16(c, a, b0_, b1_) \
    asm volatile("mma.sync.aligned.m16n8k16.row.col.f32.bf16.bf16.f32 " \
        "{%0,%1,%2,%3}, {%4,%5,%6,%7}, {%8,%9}, {%0,%1,%2,%3};" \
        : "+f"((c)[0]), "+f"((c)[1]), "+f"((c)[2]), "+f"((c)[3]) \
        : "r"((a)[0]), "r"((a)[1]), "r"((a)[2]), "r"((a)[3]), "r"(b0_), "r"(b1_))

// Producer/consumer named barrier with runtime id (alternates 1/2 by tile
// parity -> no cross-phase arrival aliasing, the round-15 deadlock cause)
#define BAR_ARRIVE_ID(id) asm volatile("bar.arrive %0, 256;" :: "r"(id) : "memory")
#define BAR_SYNC_ID(id)   asm volatile("bar.sync %0, 256;"   :: "r"(id) : "memory")

__device__ __forceinline__ unsigned short bf16_bits(__nv_bfloat16 h) {
    return *reinterpret_cast<unsigned short*>(&h);
}
__device__ __forceinline__ unsigned int pack_bf2(float a, float b) {
    return (unsigned)bf16_bits(__float2bfloat16(a)) |
           ((unsigned)bf16_bits(__float2bfloat16(b)) << 16);
}

// ---------------------------------------------------------------------------
// Prep: centers -> normalize; bf16-hi into g_B (layout unchanged)
// ---------------------------------------------------------------------------
__global__ void prep_centers(const float* __restrict__ centers) {
    int k = blockIdx.x;
    int d = threadIdx.x;
    float v = centers[k * D + d];
    float s = v * v;
    #pragma unroll
    for (int o = 16; o; o >>= 1) s += __shfl_down_sync(0xffffffffu, s, o);
    __shared__ float ws[4];
    if ((d & 31) == 0) ws[d >> 5] = s;
    __syncthreads();
    float tot  = ws[0] + ws[1] + ws[2] + ws[3];
    float norm = sqrtf(tot);
    float x = v / fmaxf(norm, 1e-12f);
    unsigned char* tile = g_B + (size_t)(k >> 7) * B_BYTES;
    int nn = k & 127;
    uint32_t off = (uint32_t)(nn * 256 + ((((d >> 3) ^ (nn & 7)) & 15) << 4) + (d & 7) * 2);
    *(unsigned short*)(tile + off) = bf16_bits(__float2bfloat16(x));
    if (d == 0) g_cnormsq[k] = tot;
}

// ---------------------------------------------------------------------------
// Main kernel: round-9 structure (TM=64, 2 CTAs/SM, double buffer, A hoisted)
// with the per-tile join split: consumers bar.arrive (non-blocking), only
// warp 0 bar.sync's before issuing the refill. IDs alternate by tile parity.
// ---------------------------------------------------------------------------
__global__ __launch_bounds__(256, 2)
void gemm_argmax_mma(const float* __restrict__ features,
                     const float* __restrict__ centers,
                     float* __restrict__ out) {
    extern __shared__ __align__(1024) unsigned char smem[];
    uint32_t sb = smem_u32(smem);
    const int tid = threadIdx.x;
    const int wid = tid >> 5, l = tid & 31;
    const int warp_m = wid >> 2, warp_n = wid & 3;

    if (tid == 0) {
        MBAR_INIT(sb + SM_CTRL + MB_RAW, 1);
        MBAR_INIT(sb + SM_CTRL + MB_B0, 1);
        MBAR_INIT(sb + SM_CTRL + MB_B1, 1);
    }
    __syncthreads();
    // Stage raw fp32 rows into the (not-yet-used) B0 region
    if (tid == 0) {
        MBAR_EXPECT_TX(sb + SM_CTRL + MB_RAW, RAW_BYTES);
        bulk_g2s(sb + SM_B0, features + (size_t)blockIdx.x * TM * D,
                 RAW_BYTES, sb + SM_CTRL + MB_RAW);
    }

    // ---- A prep: 4 threads per row, raw read from B0 staging ----
    MBAR_WAIT(sb + SM_CTRL + MB_RAW, 0);
    {
        const int row = tid >> 2, q = tid & 3;
        const float4* raw4 = (const float4*)(smem + SM_B0 + row * 512);
        float s = 0.0f;
        #pragma unroll
        for (int j = 0; j < 8; j++) {
            float4 v = raw4[q * 8 + ((j + row) & 7)];
            s += v.x * v.x + v.y * v.y + v.z * v.z + v.w * v.w;
        }
        s += __shfl_xor_sync(0xffffffffu, s, 1);
        s += __shfl_xor_sync(0xffffffffu, s, 2);
        float rinv = 1.0f / fmaxf(sqrtf(s), 1e-12f);
        if (q == 0) ((float*)(smem + SM_RINV))[row] = rinv;
        unsigned char* arow = smem + SM_AH + row * 256;
        #pragma unroll
        for (int cc = 0; cc < 4; cc++) {
            int c = q * 4 + cc;
            float4 a0 = raw4[c * 2];
            float4 a1 = raw4[c * 2 + 1];
            uint4 o;
            o.x = pack_bf2(a0.x * rinv, a0.y * rinv);
            o.y = pack_bf2(a0.z * rinv, a0.w * rinv);
            o.z = pack_bf2(a1.x * rinv, a1.y * rinv);
            o.w = pack_bf2(a1.z * rinv, a1.w * rinv);
            int fc = c ^ (row & 7);
            *(uint4*)(arow + (fc << 4)) = o;
        }
    }
    __syncthreads();   // all raw reads done; B0 region reusable

    // Kick both B buffers
    if (tid == 0) {
        MBAR_EXPECT_TX(sb + SM_CTRL + MB_B0, B_BYTES);
        bulk_g2s(sb + SM_B0, g_B, B_BYTES, sb + SM_CTRL + MB_B0);
        MBAR_EXPECT_TX(sb + SM_CTRL + MB_B1, B_BYTES);
        bulk_g2s(sb + SM_B1, g_B + B_BYTES, B_BYTES, sb + SM_CTRL + MB_B1);
    }

    const int a_row_in = (l & 7) + ((l >> 3) & 1) * 8;
    const int a_cb     = (l >> 4);
    const int b_row_in = (l & 7) + ((l >> 4) & 1) * 8;
    const int b_cb     = (l >> 3) & 1;

    // ---- Hoist ALL A fragments into registers (AH is persistent; no race) ----
    uint32_t afr[8][2][4];   // [kk][mi][frag]
    #pragma unroll
    for (int kk = 0; kk < 8; kk++) {
        #pragma unroll
        for (int mi = 0; mi < 2; mi++) {
            int row = warp_m * 32 + mi * 16 + a_row_in;
            uint32_t addr = sb + SM_AH + row * 256 +
                            (((kk * 2 + a_cb) ^ (row & 7)) << 4);
            LDSM_X4(afr[kk][mi], addr);
        }
    }

    float best[4];
    int   bidx[4];
    #pragma unroll
    for (int i = 0; i < 4; i++) { best[i] = -1e30f; bidx[i] = 0; }

    for (int t = 0; t < NTILE; t++) {
        const uint32_t bbuf = (t & 1) ? (sb + SM_B1) : (sb + SM_B0);
        MBAR_WAIT(sb + SM_CTRL + ((t & 1) ? MB_B1 : MB_B0), (t >> 1) & 1);

        float acc[2][4][4];
        #pragma unroll
        for (int mi = 0; mi < 2; mi++)
            #pragma unroll
            for (int ni = 0; ni < 4; ni++)
                #pragma unroll
                for (int e2 = 0; e2 < 4; e2++) acc[mi][ni][e2] = 0.0f;

        #pragma unroll
        for (int kk = 0; kk < 8; kk++) {
            uint32_t bfm[2][4];
            #pragma unroll
            for (int bp = 0; bp < 2; bp++) {
                int nrow = warp_n * 32 + bp * 16 + b_row_in;
                uint32_t addr = bbuf + nrow * 256 +
                                (((kk * 2 + b_cb) ^ (nrow & 7)) << 4);
                LDSM_X4(bfm[bp], addr);
            }
            #pragma unroll
            for (int mi = 0; mi < 2; mi++)
                #pragma unroll
                for (int ni = 0; ni < 4; ni++)
                    MMA_BF16(acc[mi][ni], afr[kk][mi],
                             bfm[ni >> 1][(ni & 1) * 2], bfm[ni >> 1][(ni & 1) * 2 + 1]);
        }

        // predicated fold (round-9 proven codegen)
        #pragma unroll
        for (int mi = 0; mi < 2; mi++) {
            #pragma unroll
            for (int ni = 0; ni < 4; ni++) {
                int k0 = t * TN + warp_n * 32 + ni * 8 + (l & 3) * 2;
                float c0 = acc[mi][ni][0], c1 = acc[mi][ni][1];
                float c2 = acc[mi][ni][2], c3 = acc[mi][ni][3];
                int i0 = mi * 2, i1 = mi * 2 + 1;
                if (c0 > best[i0]) { best[i0] = c0; bidx[i0] = k0; }
                if (c1 > best[i0]) { best[i0] = c1; bidx[i0] = k0 + 1; }
                if (c2 > best[i1]) { best[i1] = c2; bidx[i1] = k0; }
                if (c3 > best[i1]) { best[i1] = c3; bidx[i1] = k0 + 1; }
            }
        }

        // Split join, phase-safe: barrier id alternates with tile parity.
        // A warp cannot reach the same id again (tile t+2) before warp 0's
        // sync at tile t (t+2's MBAR needs the refill issued after that sync),
        // so arrival counts cannot alias across phases.
        if (t + 2 < NTILE) {
            const int bar_id = 1 + (t & 1);
            if (wid == 0) {
                BAR_SYNC_ID(bar_id);     // join: waits for other 7 warps
                if (l == 0) {
                    uint32_t mb = sb + SM_CTRL + ((t & 1) ? MB_B1 : MB_B0);
                    MBAR_EXPECT_TX(mb, B_BYTES);
                    bulk_g2s(bbuf, g_B + (size_t)(t + 2) * B_BYTES, B_BYTES, mb);
                }
            } else {
                BAR_ARRIVE_ID(bar_id);   // non-blocking signal
            }
        }
    }
    __syncthreads();   // all warps done with B0/B1; safe to overlay scratch

    float* red_s = (float*)(smem + SM_REDS);
    int*   red_i = (int*)(smem + SM_REDI);
    int*   bks   = (int*)(smem + SM_BKS);
    float* lsum  = (float*)(smem + SM_LSUM);
    const int e = warp_n * 4 + (l & 3);
    #pragma unroll
    for (int mi = 0; mi < 2; mi++) {
        #pragma unroll
        for (int h = 0; h < 2; h++) {
            int row = warp_m * 32 + mi * 16 + (l >> 2) + h * 8;
            red_s[row * 16 + e] = best[mi * 2 + h];
            red_i[row * 16 + e] = bidx[mi * 2 + h];
        }
    }
    __syncthreads();
    if (tid < TM) {
        float bs = -1e30f; int bk = 0;
        #pragma unroll
        for (int q = 0; q < 16; q++) {
            float s = red_s[tid * 16 + q];
            int   k = red_i[tid * 16 + q];
            if (s > bs || (s == bs && k < bk)) { bs = s; bk = k; }
        }
        bks[tid] = bk;
    }
    __syncthreads();
    // EXACT loss: 4 threads/row; features re-read from global (L2/HBM)
    {
        const int row = tid >> 2, q = tid & 3;
        const int bk  = bks[row];
        const float4* frow = (const float4*)(features + (size_t)(blockIdx.x * TM + row) * D);
        const float4* crow = (const float4*)(centers + (size_t)bk * D);
        float dot = 0.0f;
        #pragma unroll
        for (int j = 0; j < 8; j++) {
            int i4 = q * 8 + j;
            float4 a = frow[i4];
            float4 c = crow[i4];
            dot += a.x * c.x + a.y * c.y + a.z * c.z + a.w * c.w;
        }
        dot += __shfl_xor_sync(0xffffffffu, dot, 1);
        dot += __shfl_xor_sync(0xffffffffu, dot, 2);
        if (q == 0) {
            float rinv = ((float*)(smem + SM_RINV))[row];
            lsum[row] = 1.0f + g_cnormsq[bk] - 2.0f * rinv * dot;
        }
    }
    __syncthreads();
    #pragma unroll
    for (int s = TM / 2; s > 0; s >>= 1) {
        if (tid < s) lsum[tid] += lsum[tid + s];
        __syncthreads();
    }

    __shared__ unsigned int is_last;
    if (tid == 0) {
        g_partial[blockIdx.x] = lsum[0];
        __threadfence();
        is_last = (atomicAdd(&g_ctr, 1u) == NBLK - 1u);
    }
    __syncthreads();

    if (is_last) {
        __threadfence();
        double* sd = (double*)(smem + SM_SD);
        double s = 0.0;
        for (int i = tid; i < NBLK; i += 256)
            s += (double)(*(volatile float*)&g_partial[i]);
        sd[tid] = s;
        __syncthreads();
        for (int st = 128; st > 0; st >>= 1) {
            if (tid < st) sd[tid] += sd[tid + st];
            __syncthreads();
        }
        if (tid == 0) {
            out[0] = (float)(sd[0] / (double)N_FEAT);
            g_ctr = 0;
        }
    }
}

extern "C" void kernel_launch(void* const* d_in, const int* in_sizes, int n_in,
                              void* d_out, int out_size) {
    const float* features = (const float*)d_in[0];
    const float* centers  = (const float*)d_in[1];
    float* out = (float*)d_out;

    cudaFuncSetAttribute(gemm_argmax_mma,
                         cudaFuncAttributeMaxDynamicSharedMemorySize, SMEM_TOTAL);

    prep_centers<<<K, D>>>(centers);
    gemm_argmax_mma<<<NBLK, 256, SMEM_TOTAL>>>(features, centers, out);
}

// round 17
// speedup vs baseline: 1.6091x; 1.0698x over previous
#include <cuda_runtime.h>
#include <cuda_bf16.h>
#include <cstdint>
#include <math.h>

// ---------------------------------------------------------------------------
// Problem constants
// ---------------------------------------------------------------------------
#define N_FEAT 131072
#define D      128
#define K      1024
#define TM     64             // rows per CTA
#define TN     128            // centers per B-tile
#define NTILE  (K / TN)       // 8
#define NBLK   (N_FEAT / TM)  // 2048

#define RAW_BYTES (TM * D * 4)     // 32768 raw fp32 rows (staged transiently)
#define A_BYTES   (TM * D * 2)     // 16384 bf16-hi tile (256B rows, persistent)
#define B_BYTES   (TN * D * 2)     // 32768 per B tile

// SMEM map (dynamic): ctrl 1KB + AH 16KB + B0 32KB + B1 32KB = 82944 bytes
// per-CTA granule cost = ceil((82944+1024)/8192)*8192 = 90112; x2 -> 2 CTAs/SM
#define SM_CTRL 0
#define SM_RINV 256
#define SM_AH   1024
#define SM_B0   (SM_AH + A_BYTES)          // 17408; ALSO transient RAW staging
#define SM_B1   (SM_B0 + B_BYTES)          // 50176
#define SMEM_TOTAL 82944
// epilogue scratch overlays the (dead) B0 region
#define SM_REDS SM_B0
#define SM_REDI (SM_B0 + 4096)
#define SM_BKS  (SM_B0 + 8192)
#define SM_LSUM (SM_B0 + 8448)
#define SM_SD   (SM_B0 + 9216)

#define MB_RAW 0
#define MB_B0  8
#define MB_B1  16

// ---------------------------------------------------------------------------
// Device scratch
// ---------------------------------------------------------------------------
__device__ __align__(1024) unsigned char g_B[NTILE * B_BYTES];  // 256 KB
__device__ float g_cnormsq[K];
__device__ float g_partial[NBLK];
__device__ unsigned int g_ctr;

// ---------------------------------------------------------------------------
// PTX helpers
// ---------------------------------------------------------------------------
__device__ __forceinline__ uint32_t smem_u32(const void* p) {
    uint32_t a;
    asm("{ .reg .u64 t; cvta.to.shared.u64 t, %1; cvt.u32.u64 %0, t; }" : "=r"(a) : "l"(p));
    return a;
}
#define MBAR_INIT(a, c) \
    asm volatile("mbarrier.init.shared.b64 [%0], %1;" :: "r"((uint32_t)(a)), "r"((uint32_t)(c)) : "memory")
#define MBAR_EXPECT_TX(a, b) \
    asm volatile("mbarrier.arrive.expect_tx.shared.b64 _, [%0], %1;" :: "r"((uint32_t)(a)), "r"((uint32_t)(b)) : "memory")
#define MBAR_WAIT(a, ph) do { \
    uint32_t _m = (uint32_t)(a), _p = (uint32_t)(ph), _d; \
    asm volatile("{ .reg .pred p; mbarrier.try_wait.parity.acquire.cta.shared::cta.b64 p, [%1], %2; selp.b32 %0,1,0,p; }" \
        : "=r"(_d) : "r"(_m), "r"(_p) : "memory"); \
    if (!_d) { \
        asm volatile("{ .reg .pred P1; WL%=: mbarrier.try_wait.parity.acquire.cta.shared::cta.b64 P1, [%0], %1, 0x989680; @P1 bra.uni WD%=; bra.uni WL%=; WD%=: }" \
            :: "r"(_m), "r"(_p) : "memory"); \
    } \
} while (0)

__device__ __forceinline__ void bulk_g2s(uint32_t dst, const void* src,
                                         uint32_t bytes, uint32_t mbar) {
    asm volatile(
        "cp.async.bulk.shared::cta.global.mbarrier::complete_tx::bytes [%0], [%1], %2, [%3];"
        :: "r"(dst), "l"(src), "r"(bytes), "r"(mbar) : "memory");
}
#define LDSM_X4(r, a) \
    asm volatile("ldmatrix.sync.aligned.m8n8.x4.shared.b16 {%0,%1,%2,%3}, [%4];" \
        : "=r"((r)[0]), "=r"((r)[1]), "=r"((r)[2]), "=r"((r)[3]) : "r"(a))
#define MMA_BF16(c, a, b0_, b1_) \
    asm volatile("mma.sync.aligned.m16n8k16.row.col.f32.bf16.bf16.f32 " \
        "{%0,%1,%2,%3}, {%4,%5,%6,%7}, {%8,%9}, {%0,%1,%2,%3};" \
        : "+f"((c)[0]), "+f"((c)[1]), "+f"((c)[2]), "+f"((c)[3]) \
        : "r"((a)[0]), "r"((a)[1]), "r"((a)[2]), "r"((a)[3]), "r"(b0_), "r"(b1_))

__device__ __forceinline__ unsigned short bf16_bits(__nv_bfloat16 h) {
    return *reinterpret_cast<unsigned short*>(&h);
}
__device__ __forceinline__ unsigned int pack_bf2(float a, float b) {
    return (unsigned)bf16_bits(__float2bfloat16(a)) |
           ((unsigned)bf16_bits(__float2bfloat16(b)) << 16);
}

// ---------------------------------------------------------------------------
// Prep: centers -> normalize; bf16-hi into g_B
// ---------------------------------------------------------------------------
__global__ void prep_centers(const float* __restrict__ centers) {
    int k = blockIdx.x;
    int d = threadIdx.x;
    float v = centers[k * D + d];
    float s = v * v;
    #pragma unroll
    for (int o = 16; o; o >>= 1) s += __shfl_down_sync(0xffffffffu, s, o);
    __shared__ float ws[4];
    if ((d & 31) == 0) ws[d >> 5] = s;
    __syncthreads();
    float tot  = ws[0] + ws[1] + ws[2] + ws[3];
    float norm = sqrtf(tot);
    float x = v / fmaxf(norm, 1e-12f);
    unsigned char* tile = g_B + (size_t)(k >> 7) * B_BYTES;
    int nn = k & 127;
    uint32_t off = (uint32_t)(nn * 256 + ((((d >> 3) ^ (nn & 7)) & 15) << 4) + (d & 7) * 2);
    *(unsigned short*)(tile + off) = bf16_bits(__float2bfloat16(x));
    if (d == 0) g_cnormsq[k] = tot;
}

// ---------------------------------------------------------------------------
// Main kernel: TM=64, 2 CTAs/SM; double-buffer lockstep (proven optimum);
// A fragments hoisted to registers; exact fp32 loss epilogue.
// ---------------------------------------------------------------------------
__global__ __launch_bounds__(256, 2)
void gemm_argmax_mma(const float* __restrict__ features,
                     const float* __restrict__ centers,
                     float* __restrict__ out) {
    extern __shared__ __align__(1024) unsigned char smem[];
    uint32_t sb = smem_u32(smem);
    const int tid = threadIdx.x;
    const int wid = tid >> 5, l = tid & 31;
    const int warp_m = wid >> 2, warp_n = wid & 3;

    if (tid == 0) {
        MBAR_INIT(sb + SM_CTRL + MB_RAW, 1);
        MBAR_INIT(sb + SM_CTRL + MB_B0, 1);
        MBAR_INIT(sb + SM_CTRL + MB_B1, 1);
    }
    __syncthreads();
    // Stage raw fp32 rows into the (not-yet-used) B0 region
    if (tid == 0) {
        MBAR_EXPECT_TX(sb + SM_CTRL + MB_RAW, RAW_BYTES);
        bulk_g2s(sb + SM_B0, features + (size_t)blockIdx.x * TM * D,
                 RAW_BYTES, sb + SM_CTRL + MB_RAW);
    }

    // ---- A prep: 4 threads per row, raw read from B0 staging ----
    MBAR_WAIT(sb + SM_CTRL + MB_RAW, 0);
    {
        const int row = tid >> 2, q = tid & 3;
        const float4* raw4 = (const float4*)(smem + SM_B0 + row * 512);
        float s = 0.0f;
        #pragma unroll
        for (int j = 0; j < 8; j++) {
            float4 v = raw4[q * 8 + ((j + row) & 7)];
            s += v.x * v.x + v.y * v.y + v.z * v.z + v.w * v.w;
        }
        s += __shfl_xor_sync(0xffffffffu, s, 1);
        s += __shfl_xor_sync(0xffffffffu, s, 2);
        float rinv = 1.0f / fmaxf(sqrtf(s), 1e-12f);
        if (q == 0) ((float*)(smem + SM_RINV))[row] = rinv;
        unsigned char* arow = smem + SM_AH + row * 256;
        #pragma unroll
        for (int cc = 0; cc < 4; cc++) {
            int c = q * 4 + cc;
            float4 a0 = raw4[c * 2];
            float4 a1 = raw4[c * 2 + 1];
            uint4 o;
            o.x = pack_bf2(a0.x * rinv, a0.y * rinv);
            o.y = pack_bf2(a0.z * rinv, a0.w * rinv);
            o.z = pack_bf2(a1.x * rinv, a1.y * rinv);
            o.w = pack_bf2(a1.z * rinv, a1.w * rinv);
            int fc = c ^ (row & 7);
            *(uint4*)(arow + (fc << 4)) = o;
        }
    }
    __syncthreads();   // all raw reads done; B0 region reusable

    // Kick both B buffers
    if (tid == 0) {
        MBAR_EXPECT_TX(sb + SM_CTRL + MB_B0, B_BYTES);
        bulk_g2s(sb + SM_B0, g_B, B_BYTES, sb + SM_CTRL + MB_B0);
        MBAR_EXPECT_TX(sb + SM_CTRL + MB_B1, B_BYTES);
        bulk_g2s(sb + SM_B1, g_B + B_BYTES, B_BYTES, sb + SM_CTRL + MB_B1);
    }

    const int a_row_in = (l & 7) + ((l >> 3) & 1) * 8;
    const int a_cb     = (l >> 4);
    const int b_row_in = (l & 7) + ((l >> 4) & 1) * 8;
    const int b_cb     = (l >> 3) & 1;

    // ---- Hoist ALL A fragments into registers (AH persistent; no race) ----
    uint32_t afr[8][2][4];   // [kk][mi][frag]
    #pragma unroll
    for (int kk = 0; kk < 8; kk++) {
        #pragma unroll
        for (int mi = 0; mi < 2; mi++) {
            int row = warp_m * 32 + mi * 16 + a_row_in;
            uint32_t addr = sb + SM_AH + row * 256 +
                            (((kk * 2 + a_cb) ^ (row & 7)) << 4);
            LDSM_X4(afr[kk][mi], addr);
        }
    }

    float best[4];
    int   bidx[4];
    #pragma unroll
    for (int i = 0; i < 4; i++) { best[i] = -1e30f; bidx[i] = 0; }

    for (int t = 0; t < NTILE; t++) {
        const uint32_t bbuf = (t & 1) ? (sb + SM_B1) : (sb + SM_B0);
        MBAR_WAIT(sb + SM_CTRL + ((t & 1) ? MB_B1 : MB_B0), (t >> 1) & 1);

        float acc[2][4][4];
        #pragma unroll
        for (int mi = 0; mi < 2; mi++)
            #pragma unroll
            for (int ni = 0; ni < 4; ni++)
                #pragma unroll
                for (int e2 = 0; e2 < 4; e2++) acc[mi][ni][e2] = 0.0f;

        #pragma unroll
        for (int kk = 0; kk < 8; kk++) {
            uint32_t bfm[2][4];
            #pragma unroll
            for (int bp = 0; bp < 2; bp++) {
                int nrow = warp_n * 32 + bp * 16 + b_row_in;
                uint32_t addr = bbuf + nrow * 256 +
                                (((kk * 2 + b_cb) ^ (nrow & 7)) << 4);
                LDSM_X4(bfm[bp], addr);
            }
            #pragma unroll
            for (int mi = 0; mi < 2; mi++)
                #pragma unroll
                for (int ni = 0; ni < 4; ni++)
                    MMA_BF16(acc[mi][ni], afr[kk][mi],
                             bfm[ni >> 1][(ni & 1) * 2], bfm[ni >> 1][(ni & 1) * 2 + 1]);
        }

        // predicated fold (proven codegen)
        #pragma unroll
        for (int mi = 0; mi < 2; mi++) {
            #pragma unroll
            for (int ni = 0; ni < 4; ni++) {
                int k0 = t * TN + warp_n * 32 + ni * 8 + (l & 3) * 2;
                float c0 = acc[mi][ni][0], c1 = acc[mi][ni][1];
                float c2 = acc[mi][ni][2], c3 = acc[mi][ni][3];
                int i0 = mi * 2, i1 = mi * 2 + 1;
                if (c0 > best[i0]) { best[i0] = c0; bidx[i0] = k0; }
                if (c1 > best[i0]) { best[i0] = c1; bidx[i0] = k0 + 1; }
                if (c2 > best[i1]) { best[i1] = c2; bidx[i1] = k0; }
                if (c3 > best[i1]) { best[i1] = c3; bidx[i1] = k0 + 1; }
            }
        }
        // Per-tile join needed only when this buffer is about to be refilled
        // (t=6,7 have no refill; the post-loop syncthreads covers scratch reuse)
        if (t + 2 < NTILE) {
            __syncthreads();
            if (tid == 0) {
                uint32_t mb = sb + SM_CTRL + ((t & 1) ? MB_B1 : MB_B0);
                MBAR_EXPECT_TX(mb, B_BYTES);
                bulk_g2s(bbuf, g_B + (size_t)(t + 2) * B_BYTES, B_BYTES, mb);
            }
        }
    }
    __syncthreads();   // all warps done with B0/B1; safe to overlay scratch

    float* red_s = (float*)(smem + SM_REDS);
    int*   red_i = (int*)(smem + SM_REDI);
    int*   bks   = (int*)(smem + SM_BKS);
    float* lsum  = (float*)(smem + SM_LSUM);
    const int e = warp_n * 4 + (l & 3);
    #pragma unroll
    for (int mi = 0; mi < 2; mi++) {
        #pragma unroll
        for (int h = 0; h < 2; h++) {
            int row = warp_m * 32 + mi * 16 + (l >> 2) + h * 8;
            red_s[row * 16 + e] = best[mi * 2 + h];
            red_i[row * 16 + e] = bidx[mi * 2 + h];
        }
    }
    __syncthreads();
    if (tid < TM) {
        float bs = -1e30f; int bk = 0;
        #pragma unroll
        for (int q = 0; q < 16; q++) {
            float s = red_s[tid * 16 + q];
            int   k = red_i[tid * 16 + q];
            if (s > bs || (s == bs && k < bk)) { bs = s; bk = k; }
        }
        bks[tid] = bk;
    }
    __syncthreads();
    // EXACT loss: 4 threads/row; features re-read from global (L2/HBM)
    {
        const int row = tid >> 2, q = tid & 3;
        const int bk  = bks[row];
        const float4* frow = (const float4*)(features + (size_t)(blockIdx.x * TM + row) * D);
        const float4* crow = (const float4*)(centers + (size_t)bk * D);
        float dot = 0.0f;
        #pragma unroll
        for (int j = 0; j < 8; j++) {
            int i4 = q * 8 + j;
            float4 a = frow[i4];
            float4 c = crow[i4];
            dot += a.x * c.x + a.y * c.y + a.z * c.z + a.w * c.w;
        }
        dot += __shfl_xor_sync(0xffffffffu, dot, 1);
        dot += __shfl_xor_sync(0xffffffffu, dot, 2);
        if (q == 0) {
            float rinv = ((float*)(smem + SM_RINV))[row];
            lsum[row] = 1.0f + g_cnormsq[bk] - 2.0f * rinv * dot;
        }
    }
    __syncthreads();
    #pragma unroll
    for (int s = TM / 2; s > 0; s >>= 1) {
        if (tid < s) lsum[tid] += lsum[tid + s];
        __syncthreads();
    }

    __shared__ unsigned int is_last;
    if (tid == 0) {
        g_partial[blockIdx.x] = lsum[0];
        __threadfence();
        is_last = (atomicAdd(&g_ctr, 1u) == NBLK - 1u);
    }
    __syncthreads();

    if (is_last) {
        __threadfence();
        double* sd = (double*)(smem + SM_SD);
        double s = 0.0;
        for (int i = tid; i < NBLK; i += 256)
            s += (double)(*(volatile float*)&g_partial[i]);
        sd[tid] = s;
        __syncthreads();
        for (int st = 128; st > 0; st >>= 1) {
            if (tid < st) sd[tid] += sd[tid + st];
            __syncthreads();
        }
        if (tid == 0) {
            out[0] = (float)(sd[0] / (double)N_FEAT);
            g_ctr = 0;
        }
    }
}

extern "C" void kernel_launch(void* const* d_in, const int* in_sizes, int n_in,
                              void* d_out, int out_size) {
    const float* features = (const float*)d_in[0];
    const float* centers  = (const float*)d_in[1];
    float* out = (float*)d_out;

    cudaFuncSetAttribute(gemm_argmax_mma,
                         cudaFuncAttributeMaxDynamicSharedMemorySize, SMEM_TOTAL);

    prep_centers<<<K, D>>>(centers);
    gemm_argmax_mma<<<NBLK, 256, SMEM_TOTAL>>>(features, centers, out);
}